// round 9
// baseline (speedup 1.0000x reference)
#include <cuda_runtime.h>

#define NN 100000
#define EE 1600000
#define LL 3
#define CAP 96
#define NPB 64                      // nodes per block in kA/kB
#define PAD 68                      // y_s row stride (floats), 16B-aligned

typedef unsigned long long ull;

// ---------------- device scratch ----------------------------------------------
__device__ float g_h[NN * 64];
__device__ float g_z1[NN * 64];
__device__ float g_z2[NN * 64];
__device__ float g_stats[LL * 256];   // per layer: [sum1 sq1 sum2 sq2] x 64
__device__ int   g_deg[NN];
__device__ int   g_csr[(size_t)NN * CAP];

// ---------------- packed f32x2 helpers ----------------------------------------
__device__ __forceinline__ ull pack2(float a, float b) {
    ull r;
    asm("mov.b64 %0, {%1, %2};" : "=l"(r) : "f"(a), "f"(b));
    return r;
}
__device__ __forceinline__ float2 unpack2(ull v) {
    float2 r;
    asm("mov.b64 {%0, %1}, %2;" : "=f"(r.x), "=f"(r.y) : "l"(v));
    return r;
}
__device__ __forceinline__ void ffma2(ull& d, ull a, ull b) {
    asm("fma.rn.f32x2 %0, %1, %2, %0;" : "+l"(d) : "l"(a), "l"(b));
}

// ---------------- zero degree + stats -----------------------------------------
__global__ void __launch_bounds__(1024) kzero() {
    int t = blockIdx.x * 1024 + threadIdx.x;
    if (t < NN) g_deg[t] = 0;
    if (t < LL * 256) g_stats[t] = 0.f;
}

// ---------------- CSR fill ------------------------------------------------------
__global__ void __launch_bounds__(256) kfill(const int* __restrict__ ei) {
    int e = blockIdx.x * 256 + threadIdx.x;
    if (e >= EE) return;
    int s = ei[e];
    int d = ei[EE + e];
    int pos = atomicAdd(&g_deg[d], 1);
    if (pos < CAP) g_csr[(size_t)d * CAP + pos] = s;
}

// ---------------- kinit: logits = x @ fcW[0] + sum_l fcb[l] --------------------
__global__ void __launch_bounds__(256) kinit(const float* __restrict__ x,
                                             const float* __restrict__ fcW,
                                             const float* __restrict__ fcb,
                                             float* __restrict__ out) {
    __shared__ float fw[640];
    __shared__ float bsum[10];
    int tid = threadIdx.x;
    for (int i = tid; i < 640; i += 256) fw[i] = fcW[i];
    if (tid < 10) {
        float b = 0.f;
        for (int l = 0; l < LL + 1; l++) b += fcb[l * 10 + tid];
        bsum[tid] = b;
    }
    __syncthreads();
    int n = blockIdx.x * 256 + tid;
    if (n >= NN) return;
    float acc[10];
#pragma unroll
    for (int c = 0; c < 10; c++) acc[c] = bsum[c];
    const float4* x4 = ((const float4*)x) + (size_t)n * 16;
#pragma unroll
    for (int kk = 0; kk < 16; kk++) {
        float4 v = x4[kk];
        const float* r0 = fw + (kk * 4) * 10;
#pragma unroll
        for (int c = 0; c < 10; c++)
            acc[c] += v.x * r0[c] + v.y * r0[10 + c] + v.z * r0[20 + c] + v.w * r0[30 + c];
    }
#pragma unroll
    for (int c = 0; c < 10; c++) out[n * 10 + c] = acc[c];
}

// ---- shared GEMM tail: y_s(64xNPB, k-major) @ Wsh(64x64) + bias ----------------
__device__ __forceinline__ void gemm_tile(const float* y_s, const float* Wsh,
                                          const float* bs, int cg, int ng,
                                          ull acc[4][2]) {
#pragma unroll
    for (int c = 0; c < 4; c++) {
        float b = bs[4 * cg + c];
        acc[c][0] = pack2(b, b);
        acc[c][1] = acc[c][0];
    }
#pragma unroll 8
    for (int k = 0; k < 64; k++) {
        ulonglong2 a2 = ((const ulonglong2*)(y_s + k * PAD))[ng];
        float4 w = *(const float4*)(Wsh + k * 64 + cg * 4);
        ull w0 = pack2(w.x, w.x);
        ull w1 = pack2(w.y, w.y);
        ull w2 = pack2(w.z, w.z);
        ull w3 = pack2(w.w, w.w);
        ffma2(acc[0][0], a2.x, w0); ffma2(acc[0][1], a2.y, w0);
        ffma2(acc[1][0], a2.x, w1); ffma2(acc[1][1], a2.y, w1);
        ffma2(acc[2][0], a2.x, w2); ffma2(acc[2][1], a2.y, w2);
        ffma2(acc[3][0], a2.x, w3); ffma2(acc[3][1], a2.y, w3);
    }
}

// ---- shared epilogue: unpack, store z, shfl-reduce stats, atomics --------------
__device__ __forceinline__ void store_stats(ull acc[4][2], float* zout, int base,
                                            int ng, int cg, int lane,
                                            float* stat_s, float* stat_q) {
    float val[4][4];
#pragma unroll
    for (int c = 0; c < 4; c++) {
        float2 lo = unpack2(acc[c][0]);
        float2 hi = unpack2(acc[c][1]);
        val[c][0] = lo.x; val[c][1] = lo.y; val[c][2] = hi.x; val[c][3] = hi.y;
    }
    float s[4] = {0.f, 0.f, 0.f, 0.f};
    float q[4] = {0.f, 0.f, 0.f, 0.f};
#pragma unroll
    for (int i = 0; i < 4; i++) {
        int n = base + 4 * ng + i;
        if (n < NN) {
            float4 o = make_float4(val[0][i], val[1][i], val[2][i], val[3][i]);
            *(float4*)(zout + (size_t)n * 64 + 4 * cg) = o;
#pragma unroll
            for (int c = 0; c < 4; c++) {
                float v = val[c][i];
                s[c] += v;
                q[c] += v * v;
            }
        }
    }
#pragma unroll
    for (int off = 8; off >= 1; off >>= 1) {
#pragma unroll
        for (int c = 0; c < 4; c++) {
            s[c] += __shfl_xor_sync(0xffffffffu, s[c], off);
            q[c] += __shfl_xor_sync(0xffffffffu, q[c], off);
        }
    }
    if ((lane & 15) == 0) {
#pragma unroll
        for (int c = 0; c < 4; c++) {
            atomicAdd(&stat_s[4 * cg + c], s[c]);
            atomicAdd(&stat_q[4 * cg + c], q[c]);
        }
    }
}

// ======== kA: interleaved 8-node CSR gather + GEMM1 + stats1 ====================
__global__ void __launch_bounds__(256) kA(const float* __restrict__ x, int use_x,
                                          const float* __restrict__ W,
                                          const float* __restrict__ b, int layer) {
    __shared__ float y_s[64 * PAD];
    __shared__ float Wsh[4096];
    __shared__ float bs[64];
    int tid = threadIdx.x, lane = tid & 31, wid = tid >> 5;
    for (int i = tid; i < 4096; i += 256) Wsh[i] = W[i];
    if (tid < 64) bs[tid] = b[tid];
    const float* hin = use_x ? x : g_h;
    int base = blockIdx.x * NPB;

    // warp owns 8 nodes; lane owns cols 2*lane, 2*lane+1 of every node.
    const float2* hp = ((const float2*)hin) + lane;  // row n -> hp[n*32]
    float2 acc8[8];
    int   deg8[8];
    int   off8[8];
#pragma unroll
    for (int i = 0; i < 8; i++) {
        int n = base + wid * 8 + i;
        if (n < NN) {
            acc8[i] = hp[(size_t)n * 32];
            int d = g_deg[n];
            deg8[i] = d > CAP ? CAP : d;
            off8[i] = n * CAP;
        } else {
            acc8[i] = make_float2(0.f, 0.f);
            deg8[i] = 0;
            off8[i] = 0;
        }
    }
    int dmax = 0;
#pragma unroll
    for (int i = 0; i < 8; i++) dmax = max(dmax, deg8[i]);

    // joint neighbor loop: 8 independent gathers in flight per step
    for (int e = 0; e < dmax; e++) {
#pragma unroll
        for (int i = 0; i < 8; i++) {
            if (e < deg8[i]) {
                int nb = g_csr[off8[i] + e];
                float2 v = hp[(size_t)nb * 32];
                acc8[i].x += v.x;
                acc8[i].y += v.y;
            }
        }
    }

#pragma unroll
    for (int i = 0; i < 8; i++) {
        int nl = wid * 8 + i;
        y_s[(2 * lane) * PAD + nl] = acc8[i].x;
        y_s[(2 * lane + 1) * PAD + nl] = acc8[i].y;
    }
    __syncthreads();

    int ng = tid & 15, cg = tid >> 4;
    ull acc[4][2];
    gemm_tile(y_s, Wsh, bs, cg, ng, acc);
    store_stats(acc, g_z1, base, ng, cg, lane,
                g_stats + layer * 256, g_stats + layer * 256 + 64);
}

// ======== kB: BN1+ReLU -> smem(T) -> tiled GEMM2 -> z2 + stats2 =================
__global__ void __launch_bounds__(256) kB(const float* __restrict__ W,
                                          const float* __restrict__ b,
                                          const float* __restrict__ gam,
                                          const float* __restrict__ bet, int layer) {
    __shared__ float y_s[64 * PAD];
    __shared__ float Wsh[4096];
    __shared__ float bs[64], sA[64], sB[64];
    int tid = threadIdx.x, lane = tid & 31, wid = tid >> 5;
    for (int i = tid; i < 4096; i += 256) Wsh[i] = W[i];
    if (tid < 64) {
        float s = g_stats[layer * 256 + tid];
        float q = g_stats[layer * 256 + 64 + tid];
        float mu = s * (1.f / NN);
        float var = q * (1.f / NN) - mu * mu;
        float a = rsqrtf(var + 1e-5f) * gam[tid];
        sA[tid] = a;
        sB[tid] = bet[tid] - mu * a;
        bs[tid] = b[tid];
    }
    __syncthreads();
    int base = blockIdx.x * NPB;

#pragma unroll 2
    for (int i = 0; i < 8; i++) {
        int nl = wid * 8 + i;
        int n = base + nl;
        float yx = 0.f, yy = 0.f;
        if (n < NN) {
            float2 v = ((const float2*)(g_z1 + (size_t)n * 64))[lane];
            int k0 = 2 * lane;
            yx = fmaxf(fmaf(v.x, sA[k0], sB[k0]), 0.f);
            yy = fmaxf(fmaf(v.y, sA[k0 + 1], sB[k0 + 1]), 0.f);
        }
        y_s[(2 * lane) * PAD + nl] = yx;
        y_s[(2 * lane + 1) * PAD + nl] = yy;
    }
    __syncthreads();

    int ng = tid & 15, cg = tid >> 4;
    ull acc[4][2];
    gemm_tile(y_s, Wsh, bs, cg, ng, acc);
    store_stats(acc, g_z2, base, ng, cg, lane,
                g_stats + layer * 256 + 128, g_stats + layer * 256 + 192);
}

// ======== kC: BN2+ReLU -> h; logits += h @ fcW[layer+1]; optional softmax =======
__global__ void __launch_bounds__(256) kC(const float* __restrict__ gam,
                                          const float* __restrict__ bet,
                                          const float* __restrict__ fcW,
                                          int layer, int final_layer,
                                          float* __restrict__ out) {
    __shared__ float fw[640];
    __shared__ float sA[64], sB[64];
    int tid = threadIdx.x;
    const float* fsrc = fcW + (layer + 1) * 640;
    for (int i = tid; i < 640; i += 256) fw[i] = fsrc[i];
    if (tid < 64) {
        float s = g_stats[layer * 256 + 128 + tid];
        float q = g_stats[layer * 256 + 192 + tid];
        float mu = s * (1.f / NN);
        float var = q * (1.f / NN) - mu * mu;
        float a = rsqrtf(var + 1e-5f) * gam[tid];
        sA[tid] = a;
        sB[tid] = bet[tid] - mu * a;
    }
    __syncthreads();
    int n = blockIdx.x * 256 + tid;
    if (n >= NN) return;
    float o[10];
#pragma unroll
    for (int c = 0; c < 10; c++) o[c] = out[n * 10 + c];
    const float4* z4 = ((const float4*)g_z2) + (size_t)n * 16;
    float4* hout = ((float4*)g_h) + (size_t)n * 16;
#pragma unroll
    for (int kk = 0; kk < 16; kk++) {
        float4 v = z4[kk];
        int k0 = kk * 4;
        float h0 = fmaxf(fmaf(v.x, sA[k0 + 0], sB[k0 + 0]), 0.f);
        float h1 = fmaxf(fmaf(v.y, sA[k0 + 1], sB[k0 + 1]), 0.f);
        float h2 = fmaxf(fmaf(v.z, sA[k0 + 2], sB[k0 + 2]), 0.f);
        float h3 = fmaxf(fmaf(v.w, sA[k0 + 3], sB[k0 + 3]), 0.f);
        if (!final_layer) hout[kk] = make_float4(h0, h1, h2, h3);
        const float* r0 = fw + k0 * 10;
#pragma unroll
        for (int c = 0; c < 10; c++)
            o[c] += h0 * r0[c] + h1 * r0[10 + c] + h2 * r0[20 + c] + h3 * r0[30 + c];
    }
    if (final_layer) {
        float m = -1e30f;
#pragma unroll
        for (int c = 0; c < 10; c++) m = fmaxf(m, o[c]);
        float s = 0.f;
#pragma unroll
        for (int c = 0; c < 10; c++) s += expf(o[c] - m);
        float lse = m + logf(s);
#pragma unroll
        for (int c = 0; c < 10; c++) o[c] -= lse;
    }
#pragma unroll
    for (int c = 0; c < 10; c++) out[n * 10 + c] = o[c];
}

// ---------------- launch --------------------------------------------------------
extern "C" void kernel_launch(void* const* d_in, const int* in_sizes, int n_in,
                              void* d_out, int out_size) {
    const float* x   = (const float*)d_in[0];
    const int*   ei  = (const int*)d_in[1];
    const float* W1  = (const float*)d_in[2];
    const float* b1  = (const float*)d_in[3];
    const float* g1  = (const float*)d_in[4];
    const float* be1 = (const float*)d_in[5];
    const float* W2  = (const float*)d_in[6];
    const float* b2  = (const float*)d_in[7];
    const float* gbn = (const float*)d_in[8];
    const float* bbn = (const float*)d_in[9];
    const float* fcW = (const float*)d_in[10];
    const float* fcb = (const float*)d_in[11];
    float* out = (float*)d_out;

    const int AB = (NN + NPB - 1) / NPB;  // 1563
    const int CB = (NN + 255) / 256;      // 391

    kzero<<<(NN + 1023) / 1024, 1024>>>();
    kfill<<<(EE + 255) / 256, 256>>>(ei);
    kinit<<<CB, 256>>>(x, fcW, fcb, out);
    for (int l = 0; l < LL; l++) {
        int use_x = (l == 0) ? 1 : 0;
        kA<<<AB, 256>>>(x, use_x, W1 + l * 4096, b1 + l * 64, l);
        kB<<<AB, 256>>>(W2 + l * 4096, b2 + l * 64, g1 + l * 64, be1 + l * 64, l);
        kC<<<CB, 256>>>(gbn + l * 64, bbn + l * 64, fcW, l, (l == LL - 1) ? 1 : 0, out);
    }
}

// round 11
// speedup vs baseline: 1.0108x; 1.0108x over previous
#include <cuda_runtime.h>
#include <cuda_fp16.h>

#define NN 100000
#define EE 1600000
#define LL 3
#define CAP 96
#define NPB 64                      // nodes per block in kA/kB
#define PAD 68                      // y_s row stride (floats), 16B-aligned

typedef unsigned long long ull;

// ---------------- device scratch ----------------------------------------------
__device__ __half g_hh[NN * 64];      // h (layer>=1) or x (layer 0) in fp16
__device__ float g_z1[NN * 64];
__device__ float g_z2[NN * 64];
__device__ float g_stats[LL * 256];   // per layer: [sum1 sq1 sum2 sq2] x 64
__device__ int   g_deg[NN];
__device__ int   g_csr[(size_t)NN * CAP];

// ---------------- packed f32x2 helpers ----------------------------------------
__device__ __forceinline__ ull pack2(float a, float b) {
    ull r;
    asm("mov.b64 %0, {%1, %2};" : "=l"(r) : "f"(a), "f"(b));
    return r;
}
__device__ __forceinline__ float2 unpack2(ull v) {
    float2 r;
    asm("mov.b64 {%0, %1}, %2;" : "=f"(r.x), "=f"(r.y) : "l"(v));
    return r;
}
__device__ __forceinline__ void ffma2(ull& d, ull a, ull b) {
    asm("fma.rn.f32x2 %0, %1, %2, %0;" : "+l"(d) : "l"(a), "l"(b));
}

// ---------------- zero degree + stats -----------------------------------------
__global__ void __launch_bounds__(1024) kzero() {
    int t = blockIdx.x * 1024 + threadIdx.x;
    if (t < NN) g_deg[t] = 0;
    if (t < LL * 256) g_stats[t] = 0.f;
}

// ---------------- CSR fill ------------------------------------------------------
__global__ void __launch_bounds__(256) kfill(const int* __restrict__ ei) {
    int e = blockIdx.x * 256 + threadIdx.x;
    if (e >= EE) return;
    int s = ei[e];
    int d = ei[EE + e];
    int pos = atomicAdd(&g_deg[d], 1);
    if (pos < CAP) g_csr[(size_t)d * CAP + pos] = s;
}

// ---- kinit: logits = x @ fcW[0] + sum_l fcb[l]; stage x as fp16 ----------------
__global__ void __launch_bounds__(256) kinit(const float* __restrict__ x,
                                             const float* __restrict__ fcW,
                                             const float* __restrict__ fcb,
                                             float* __restrict__ out) {
    __shared__ float fw[640];
    __shared__ float bsum[10];
    int tid = threadIdx.x;
    for (int i = tid; i < 640; i += 256) fw[i] = fcW[i];
    if (tid < 10) {
        float b = 0.f;
        for (int l = 0; l < LL + 1; l++) b += fcb[l * 10 + tid];
        bsum[tid] = b;
    }
    __syncthreads();
    int n = blockIdx.x * 256 + tid;
    if (n >= NN) return;
    float acc[10];
#pragma unroll
    for (int c = 0; c < 10; c++) acc[c] = bsum[c];
    const float4* x4 = ((const float4*)x) + (size_t)n * 16;
    __half2* hx = ((__half2*)g_hh) + (size_t)n * 32;
#pragma unroll
    for (int kk = 0; kk < 16; kk++) {
        float4 v = x4[kk];
        hx[2 * kk] = __floats2half2_rn(v.x, v.y);
        hx[2 * kk + 1] = __floats2half2_rn(v.z, v.w);
        const float* r0 = fw + (kk * 4) * 10;
#pragma unroll
        for (int c = 0; c < 10; c++)
            acc[c] += v.x * r0[c] + v.y * r0[10 + c] + v.z * r0[20 + c] + v.w * r0[30 + c];
    }
#pragma unroll
    for (int c = 0; c < 10; c++) out[n * 10 + c] = acc[c];
}

// ---- shared GEMM tail: y_s(64xNPB, k-major) @ Wsh(64x64) + bias ----------------
__device__ __forceinline__ void gemm_tile(const float* y_s, const float* Wsh,
                                          const float* bs, int cg, int ng,
                                          ull acc[4][2]) {
#pragma unroll
    for (int c = 0; c < 4; c++) {
        float b = bs[4 * cg + c];
        acc[c][0] = pack2(b, b);
        acc[c][1] = acc[c][0];
    }
#pragma unroll 8
    for (int k = 0; k < 64; k++) {
        ulonglong2 a2 = ((const ulonglong2*)(y_s + k * PAD))[ng];
        float4 w = *(const float4*)(Wsh + k * 64 + cg * 4);
        ull w0 = pack2(w.x, w.x);
        ull w1 = pack2(w.y, w.y);
        ull w2 = pack2(w.z, w.z);
        ull w3 = pack2(w.w, w.w);
        ffma2(acc[0][0], a2.x, w0); ffma2(acc[0][1], a2.y, w0);
        ffma2(acc[1][0], a2.x, w1); ffma2(acc[1][1], a2.y, w1);
        ffma2(acc[2][0], a2.x, w2); ffma2(acc[2][1], a2.y, w2);
        ffma2(acc[3][0], a2.x, w3); ffma2(acc[3][1], a2.y, w3);
    }
}

// ---- shared epilogue: unpack, store z, shfl-reduce stats, atomics --------------
__device__ __forceinline__ void store_stats(ull acc[4][2], float* zout, int base,
                                            int ng, int cg, int lane,
                                            float* stat_s, float* stat_q) {
    float val[4][4];
#pragma unroll
    for (int c = 0; c < 4; c++) {
        float2 lo = unpack2(acc[c][0]);
        float2 hi = unpack2(acc[c][1]);
        val[c][0] = lo.x; val[c][1] = lo.y; val[c][2] = hi.x; val[c][3] = hi.y;
    }
    float s[4] = {0.f, 0.f, 0.f, 0.f};
    float q[4] = {0.f, 0.f, 0.f, 0.f};
#pragma unroll
    for (int i = 0; i < 4; i++) {
        int n = base + 4 * ng + i;
        if (n < NN) {
            float4 o = make_float4(val[0][i], val[1][i], val[2][i], val[3][i]);
            *(float4*)(zout + (size_t)n * 64 + 4 * cg) = o;
#pragma unroll
            for (int c = 0; c < 4; c++) {
                float v = val[c][i];
                s[c] += v;
                q[c] += v * v;
            }
        }
    }
#pragma unroll
    for (int off = 8; off >= 1; off >>= 1) {
#pragma unroll
        for (int c = 0; c < 4; c++) {
            s[c] += __shfl_xor_sync(0xffffffffu, s[c], off);
            q[c] += __shfl_xor_sync(0xffffffffu, q[c], off);
        }
    }
    if ((lane & 15) == 0) {
#pragma unroll
        for (int c = 0; c < 4; c++) {
            atomicAdd(&stat_s[4 * cg + c], s[c]);
            atomicAdd(&stat_q[4 * cg + c], q[c]);
        }
    }
}

// ======== kA: fp16 CSR gather (warp/node, 4-unroll) + GEMM1 + stats1 ============
__global__ void __launch_bounds__(256) kA(const float* __restrict__ W,
                                          const float* __restrict__ b, int layer) {
    __shared__ float y_s[64 * PAD];
    __shared__ float Wsh[4096];
    __shared__ float bs[64];
    int tid = threadIdx.x, lane = tid & 31, wid = tid >> 5;
    for (int i = tid; i < 4096; i += 256) Wsh[i] = W[i];
    if (tid < 64) bs[tid] = b[tid];
    int base = blockIdx.x * NPB;

    const __half2* hp = ((const __half2*)g_hh) + lane;  // row n -> hp[n*32]

#pragma unroll 1
    for (int i = 0; i < 8; i++) {
        int nl = wid * 8 + i;
        int n = base + nl;
        float sx = 0.f, sy = 0.f;
        if (n < NN) {
            float2 v = __half22float2(hp[(size_t)n * 32]);
            sx = v.x; sy = v.y;
            int deg = g_deg[n];
            if (deg > CAP) deg = CAP;
            const int* adj = g_csr + (size_t)n * CAP;
            float a1x = 0.f, a1y = 0.f, a2x = 0.f, a2y = 0.f, a3x = 0.f, a3y = 0.f;
            int e = 0;
            for (; e + 4 <= deg; e += 4) {
                int4 nb = *(const int4*)(adj + e);
                float2 v0 = __half22float2(hp[(size_t)nb.x * 32]);
                float2 v1 = __half22float2(hp[(size_t)nb.y * 32]);
                float2 v2 = __half22float2(hp[(size_t)nb.z * 32]);
                float2 v3 = __half22float2(hp[(size_t)nb.w * 32]);
                sx += v0.x; sy += v0.y;
                a1x += v1.x; a1y += v1.y;
                a2x += v2.x; a2y += v2.y;
                a3x += v3.x; a3y += v3.y;
            }
            for (; e < deg; e++) {
                float2 v0 = __half22float2(hp[(size_t)adj[e] * 32]);
                sx += v0.x; sy += v0.y;
            }
            sx += (a1x + a2x) + a3x;
            sy += (a1y + a2y) + a3y;
        }
        y_s[(2 * lane) * PAD + nl] = sx;
        y_s[(2 * lane + 1) * PAD + nl] = sy;
    }
    __syncthreads();

    int ng = tid & 15, cg = tid >> 4;
    ull acc[4][2];
    gemm_tile(y_s, Wsh, bs, cg, ng, acc);
    store_stats(acc, g_z1, base, ng, cg, lane,
                g_stats + layer * 256, g_stats + layer * 256 + 64);
}

// ======== kB: BN1+ReLU -> smem(T) -> tiled GEMM2 -> z2 + stats2 =================
__global__ void __launch_bounds__(256) kB(const float* __restrict__ W,
                                          const float* __restrict__ b,
                                          const float* __restrict__ gam,
                                          const float* __restrict__ bet, int layer) {
    __shared__ float y_s[64 * PAD];
    __shared__ float Wsh[4096];
    __shared__ float bs[64], sA[64], sB[64];
    int tid = threadIdx.x, lane = tid & 31, wid = tid >> 5;
    for (int i = tid; i < 4096; i += 256) Wsh[i] = W[i];
    if (tid < 64) {
        float s = g_stats[layer * 256 + tid];
        float q = g_stats[layer * 256 + 64 + tid];
        float mu = s * (1.f / NN);
        float var = q * (1.f / NN) - mu * mu;
        float a = rsqrtf(var + 1e-5f) * gam[tid];
        sA[tid] = a;
        sB[tid] = bet[tid] - mu * a;
        bs[tid] = b[tid];
    }
    __syncthreads();
    int base = blockIdx.x * NPB;

#pragma unroll 2
    for (int i = 0; i < 8; i++) {
        int nl = wid * 8 + i;
        int n = base + nl;
        float yx = 0.f, yy = 0.f;
        if (n < NN) {
            float2 v = ((const float2*)(g_z1 + (size_t)n * 64))[lane];
            int k0 = 2 * lane;
            yx = fmaxf(fmaf(v.x, sA[k0], sB[k0]), 0.f);
            yy = fmaxf(fmaf(v.y, sA[k0 + 1], sB[k0 + 1]), 0.f);
        }
        y_s[(2 * lane) * PAD + nl] = yx;
        y_s[(2 * lane + 1) * PAD + nl] = yy;
    }
    __syncthreads();

    int ng = tid & 15, cg = tid >> 4;
    ull acc[4][2];
    gemm_tile(y_s, Wsh, bs, cg, ng, acc);
    store_stats(acc, g_z2, base, ng, cg, lane,
                g_stats + layer * 256 + 128, g_stats + layer * 256 + 192);
}

// ==== kC: BN2+ReLU -> h(fp16); logits += h @ fcW[layer+1]; optional softmax =====
__global__ void __launch_bounds__(256) kC(const float* __restrict__ gam,
                                          const float* __restrict__ bet,
                                          const float* __restrict__ fcW,
                                          int layer, int final_layer,
                                          float* __restrict__ out) {
    __shared__ float fw[640];
    __shared__ float sA[64], sB[64];
    int tid = threadIdx.x;
    const float* fsrc = fcW + (layer + 1) * 640;
    for (int i = tid; i < 640; i += 256) fw[i] = fsrc[i];
    if (tid < 64) {
        float s = g_stats[layer * 256 + 128 + tid];
        float q = g_stats[layer * 256 + 192 + tid];
        float mu = s * (1.f / NN);
        float var = q * (1.f / NN) - mu * mu;
        float a = rsqrtf(var + 1e-5f) * gam[tid];
        sA[tid] = a;
        sB[tid] = bet[tid] - mu * a;
    }
    __syncthreads();
    int n = blockIdx.x * 256 + tid;
    if (n >= NN) return;
    float o[10];
#pragma unroll
    for (int c = 0; c < 10; c++) o[c] = out[n * 10 + c];
    const float4* z4 = ((const float4*)g_z2) + (size_t)n * 16;
    __half2* hout = ((__half2*)g_hh) + (size_t)n * 32;
#pragma unroll
    for (int kk = 0; kk < 16; kk++) {
        float4 v = z4[kk];
        int k0 = kk * 4;
        float h0 = fmaxf(fmaf(v.x, sA[k0 + 0], sB[k0 + 0]), 0.f);
        float h1 = fmaxf(fmaf(v.y, sA[k0 + 1], sB[k0 + 1]), 0.f);
        float h2 = fmaxf(fmaf(v.z, sA[k0 + 2], sB[k0 + 2]), 0.f);
        float h3 = fmaxf(fmaf(v.w, sA[k0 + 3], sB[k0 + 3]), 0.f);
        if (!final_layer) {
            hout[2 * kk] = __floats2half2_rn(h0, h1);
            hout[2 * kk + 1] = __floats2half2_rn(h2, h3);
        }
        const float* r0 = fw + k0 * 10;
#pragma unroll
        for (int c = 0; c < 10; c++)
            o[c] += h0 * r0[c] + h1 * r0[10 + c] + h2 * r0[20 + c] + h3 * r0[30 + c];
    }
    if (final_layer) {
        float m = -1e30f;
#pragma unroll
        for (int c = 0; c < 10; c++) m = fmaxf(m, o[c]);
        float s = 0.f;
#pragma unroll
        for (int c = 0; c < 10; c++) s += expf(o[c] - m);
        float lse = m + logf(s);
#pragma unroll
        for (int c = 0; c < 10; c++) o[c] -= lse;
    }
#pragma unroll
    for (int c = 0; c < 10; c++) out[n * 10 + c] = o[c];
}

// ---------------- launch --------------------------------------------------------
extern "C" void kernel_launch(void* const* d_in, const int* in_sizes, int n_in,
                              void* d_out, int out_size) {
    const float* x   = (const float*)d_in[0];
    const int*   ei  = (const int*)d_in[1];
    const float* W1  = (const float*)d_in[2];
    const float* b1  = (const float*)d_in[3];
    const float* g1  = (const float*)d_in[4];
    const float* be1 = (const float*)d_in[5];
    const float* W2  = (const float*)d_in[6];
    const float* b2  = (const float*)d_in[7];
    const float* gbn = (const float*)d_in[8];
    const float* bbn = (const float*)d_in[9];
    const float* fcW = (const float*)d_in[10];
    const float* fcb = (const float*)d_in[11];
    float* out = (float*)d_out;

    const int AB = (NN + NPB - 1) / NPB;  // 1563
    const int CB = (NN + 255) / 256;      // 391

    kzero<<<(NN + 1023) / 1024, 1024>>>();
    kfill<<<(EE + 255) / 256, 256>>>(ei);
    kinit<<<CB, 256>>>(x, fcW, fcb, out);
    for (int l = 0; l < LL; l++) {
        kA<<<AB, 256>>>(W1 + l * 4096, b1 + l * 64, l);
        kB<<<AB, 256>>>(W2 + l * 4096, b2 + l * 64, g1 + l * 64, be1 + l * 64, l);
        kC<<<CB, 256>>>(gbn + l * 64, bbn + l * 64, fcW, l, (l == LL - 1) ? 1 : 0, out);
    }
}

// round 16
// speedup vs baseline: 1.1926x; 1.1798x over previous
#include <cuda_runtime.h>

#define NN 100000
#define EE 1600000
#define LL 3
#define CAP 96
#define GNPB 128
#define GPAD 132
#define ZPAD 66

typedef unsigned long long ull;

__device__ float g_h[NN * 64];
__device__ float g_agg[NN * 64];
__device__ float g_z1[NN * 64];
__device__ float g_z2[NN * 64];
__device__ float g_stats[LL * 256];
__device__ int   g_deg[NN];
__device__ int   g_csr[(size_t)NN * CAP];

__device__ __forceinline__ ull pack2(float a, float b) {
    ull r;
    asm("mov.b64 %0, {%1, %2};" : "=l"(r) : "f"(a), "f"(b));
    return r;
}
__device__ __forceinline__ float2 unpack2(ull v) {
    float2 r;
    asm("mov.b64 {%0, %1}, %2;" : "=f"(r.x), "=f"(r.y) : "l"(v));
    return r;
}
__device__ __forceinline__ void ffma2(ull& d, ull a, ull b) {
    asm("fma.rn.f32x2 %0, %1, %2, %0;" : "+l"(d) : "l"(a), "l"(b));
}

__global__ void __launch_bounds__(1024) kzero() {
    int t = blockIdx.x * 1024 + threadIdx.x;
    if (t < NN) g_deg[t] = 0;
    if (t < LL * 256) g_stats[t] = 0.f;
}

__global__ void __launch_bounds__(256) kfill(const int* __restrict__ ei) {
    int e = blockIdx.x * 256 + threadIdx.x;
    if (e >= EE) return;
    int s = ei[e];
    int d = ei[EE + e];
    int pos = atomicAdd(&g_deg[d], 1);
    if (pos < CAP) g_csr[(size_t)d * CAP + pos] = s;
}

__global__ void __launch_bounds__(256) kinit(const float* __restrict__ x,
                                             const float* __restrict__ fcW,
                                             const float* __restrict__ fcb,
                                             float* __restrict__ out) {
    __shared__ float fw[640];
    __shared__ float bsum[10];
    int tid = threadIdx.x;
    for (int i = tid; i < 640; i += 256) fw[i] = fcW[i];
    if (tid < 10) {
        float b = 0.f;
        for (int l = 0; l < LL + 1; l++) b += fcb[l * 10 + tid];
        bsum[tid] = b;
    }
    __syncthreads();
    int n = blockIdx.x * 256 + tid;
    if (n >= NN) return;
    float acc[10];
#pragma unroll
    for (int c = 0; c < 10; c++) acc[c] = bsum[c];
    const float4* x4 = ((const float4*)x) + (size_t)n * 16;
#pragma unroll
    for (int kk = 0; kk < 16; kk++) {
        float4 v = x4[kk];
        const float* r0 = fw + (kk * 4) * 10;
#pragma unroll
        for (int c = 0; c < 10; c++)
            acc[c] += v.x * r0[c] + v.y * r0[10 + c] + v.z * r0[20 + c] + v.w * r0[30 + c];
    }
#pragma unroll
    for (int c = 0; c < 10; c++) out[n * 10 + c] = acc[c];
}

__global__ void __launch_bounds__(256) kgather(const float* __restrict__ x, int use_x) {
    int w = (blockIdx.x * 256 + threadIdx.x) >> 5;
    int l = threadIdx.x & 31;
    if (w >= NN) return;
    const float* hin = use_x ? x : g_h;
    int deg = g_deg[w];
    if (deg > CAP) deg = CAP;
    const int* adj = g_csr + (size_t)w * CAP;
    float2 self = ((const float2*)(hin + (size_t)w * 64))[l];
    float a0x = self.x, a0y = self.y;
    float a1x = 0.f, a1y = 0.f, a2x = 0.f, a2y = 0.f, a3x = 0.f, a3y = 0.f;
    int e = 0;
    for (; e + 4 <= deg; e += 4) {
        int i0 = adj[e], i1 = adj[e + 1], i2 = adj[e + 2], i3 = adj[e + 3];
        float2 v0 = ((const float2*)(hin + (size_t)i0 * 64))[l];
        float2 v1 = ((const float2*)(hin + (size_t)i1 * 64))[l];
        float2 v2 = ((const float2*)(hin + (size_t)i2 * 64))[l];
        float2 v3 = ((const float2*)(hin + (size_t)i3 * 64))[l];
        a0x += v0.x; a0y += v0.y;
        a1x += v1.x; a1y += v1.y;
        a2x += v2.x; a2y += v2.y;
        a3x += v3.x; a3y += v3.y;
    }
    for (; e < deg; e++) {
        float2 v0 = ((const float2*)(hin + (size_t)adj[e] * 64))[l];
        a0x += v0.x; a0y += v0.y;
    }
    float2 r;
    r.x = (a0x + a1x) + (a2x + a3x);
    r.y = (a0y + a1y) + (a2y + a3y);
    ((float2*)g_agg)[(size_t)w * 32 + l] = r;
}

__global__ void __launch_bounds__(128) kG(const float* __restrict__ W,
                                          const float* __restrict__ b,
                                          const float* __restrict__ gam,
                                          const float* __restrict__ bet,
                                          int layer, int mode) {
    __shared__ float y_s[64 * GPAD];
    __shared__ float Wsh[4096];
    __shared__ float bs[64], sA[64], sB[64];
    const float* in = mode ? g_z1 : g_agg;
    float* zout = mode ? g_z2 : g_z1;
    int tid = threadIdx.x, lane = tid & 31;
    const float4* Wg = (const float4*)W;
    for (int i = tid; i < 1024; i += 128) ((float4*)Wsh)[i] = Wg[i];
    if (tid < 64) {
        bs[tid] = b[tid];
        if (mode) {
            float s = g_stats[layer * 256 + tid];
            float q = g_stats[layer * 256 + 64 + tid];
            float mu = s * (1.f / NN);
            float var = q * (1.f / NN) - mu * mu;
            float a = rsqrtf(var + 1e-5f) * gam[tid];
            sA[tid] = a;
            sB[tid] = bet[tid] - mu * a;
        }
    }
    __syncthreads();

    int base = blockIdx.x * GNPB;

    {
        int nl0 = tid >> 4;
        int c4 = tid & 15;
        int k0 = 4 * c4;
#pragma unroll 4
        for (int p = 0; p < 16; p++) {
            int nl = p * 8 + nl0;
            int n = base + nl;
            float4 v = make_float4(0.f, 0.f, 0.f, 0.f);
            if (n < NN) {
                v = *(const float4*)(in + (size_t)n * 64 + k0);
                if (mode) {
                    v.x = fmaxf(fmaf(v.x, sA[k0 + 0], sB[k0 + 0]), 0.f);
                    v.y = fmaxf(fmaf(v.y, sA[k0 + 1], sB[k0 + 1]), 0.f);
                    v.z = fmaxf(fmaf(v.z, sA[k0 + 2], sB[k0 + 2]), 0.f);
                    v.w = fmaxf(fmaf(v.w, sA[k0 + 3], sB[k0 + 3]), 0.f);
                }
            }
            y_s[(k0 + 0) * GPAD + nl] = v.x;
            y_s[(k0 + 1) * GPAD + nl] = v.y;
            y_s[(k0 + 2) * GPAD + nl] = v.z;
            y_s[(k0 + 3) * GPAD + nl] = v.w;
        }
    }
    __syncthreads();

    int ng = tid & 15;
    int cg = tid >> 4;
    ull acc[8][4];
#pragma unroll
    for (int c = 0; c < 8; c++) {
        float bb = bs[8 * cg + c];
        ull bp = pack2(bb, bb);
        acc[c][0] = bp; acc[c][1] = bp; acc[c][2] = bp; acc[c][3] = bp;
    }
#pragma unroll 8
    for (int k = 0; k < 64; k++) {
        const float* yr = y_s + k * GPAD;
        ulonglong2 alo = *(const ulonglong2*)(yr + 4 * ng);
        ulonglong2 ahi = *(const ulonglong2*)(yr + 64 + 4 * ng);
        float4 w0 = *(const float4*)(Wsh + k * 64 + 8 * cg);
        float4 w1 = *(const float4*)(Wsh + k * 64 + 8 * cg + 4);
        ull wp;
        wp = pack2(w0.x, w0.x);
        ffma2(acc[0][0], alo.x, wp); ffma2(acc[0][1], alo.y, wp);
        ffma2(acc[0][2], ahi.x, wp); ffma2(acc[0][3], ahi.y, wp);
        wp = pack2(w0.y, w0.y);
        ffma2(acc[1][0], alo.x, wp); ffma2(acc[1][1], alo.y, wp);
        ffma2(acc[1][2], ahi.x, wp); ffma2(acc[1][3], ahi.y, wp);
        wp = pack2(w0.z, w0.z);
        ffma2(acc[2][0], alo.x, wp); ffma2(acc[2][1], alo.y, wp);
        ffma2(acc[2][2], ahi.x, wp); ffma2(acc[2][3], ahi.y, wp);
        wp = pack2(w0.w, w0.w);
        ffma2(acc[3][0], alo.x, wp); ffma2(acc[3][1], alo.y, wp);
        ffma2(acc[3][2], ahi.x, wp); ffma2(acc[3][3], ahi.y, wp);
        wp = pack2(w1.x, w1.x);
        ffma2(acc[4][0], alo.x, wp); ffma2(acc[4][1], alo.y, wp);
        ffma2(acc[4][2], ahi.x, wp); ffma2(acc[4][3], ahi.y, wp);
        wp = pack2(w1.y, w1.y);
        ffma2(acc[5][0], alo.x, wp); ffma2(acc[5][1], alo.y, wp);
        ffma2(acc[5][2], ahi.x, wp); ffma2(acc[5][3], ahi.y, wp);
        wp = pack2(w1.z, w1.z);
        ffma2(acc[6][0], alo.x, wp); ffma2(acc[6][1], alo.y, wp);
        ffma2(acc[6][2], ahi.x, wp); ffma2(acc[6][3], ahi.y, wp);
        wp = pack2(w1.w, w1.w);
        ffma2(acc[7][0], alo.x, wp); ffma2(acc[7][1], alo.y, wp);
        ffma2(acc[7][2], ahi.x, wp); ffma2(acc[7][3], ahi.y, wp);
    }

    float val[8][8];
#pragma unroll
    for (int c = 0; c < 8; c++) {
        float2 p0 = unpack2(acc[c][0]);
        float2 p1 = unpack2(acc[c][1]);
        float2 p2 = unpack2(acc[c][2]);
        float2 p3 = unpack2(acc[c][3]);
        val[c][0] = p0.x; val[c][1] = p0.y; val[c][2] = p1.x; val[c][3] = p1.y;
        val[c][4] = p2.x; val[c][5] = p2.y; val[c][6] = p3.x; val[c][7] = p3.y;
    }

    {
        float s[8] = {0, 0, 0, 0, 0, 0, 0, 0};
        float q[8] = {0, 0, 0, 0, 0, 0, 0, 0};
#pragma unroll
        for (int i = 0; i < 8; i++) {
            int nl = (i < 4) ? (4 * ng + i) : (64 + 4 * ng + (i - 4));
            if (base + nl < NN) {
#pragma unroll
                for (int c = 0; c < 8; c++) {
                    float v = val[c][i];
                    s[c] += v;
                    q[c] += v * v;
                }
            }
        }
#pragma unroll
        for (int off = 8; off >= 1; off >>= 1) {
#pragma unroll
            for (int c = 0; c < 8; c++) {
                s[c] += __shfl_xor_sync(0xffffffffu, s[c], off);
                q[c] += __shfl_xor_sync(0xffffffffu, q[c], off);
            }
        }
        if ((lane & 15) == 0) {
            float* st = g_stats + layer * 256 + (mode ? 128 : 0);
#pragma unroll
            for (int c = 0; c < 8; c++) {
                atomicAdd(&st[8 * cg + c], s[c]);
                atomicAdd(&st[64 + 8 * cg + c], q[c]);
            }
        }
    }

    __syncthreads();
    float* z_s = y_s;
#pragma unroll
    for (int i = 0; i < 8; i++) {
        int nl = (i < 4) ? (4 * ng + i) : (64 + 4 * ng + (i - 4));
        float* row = z_s + nl * ZPAD + 8 * cg;
#pragma unroll
        for (int t = 0; t < 4; t++)
            *(float2*)(row + 2 * t) = make_float2(val[2 * t][i], val[2 * t + 1][i]);
    }
    __syncthreads();
    {
        int r0 = tid >> 5;
#pragma unroll 8
        for (int p = 0; p < 32; p++) {
            int r = p * 4 + r0;
            int n = base + r;
            if (n < NN) {
                float2 v = *(const float2*)(z_s + r * ZPAD + 2 * lane);
                ((float2*)zout)[(size_t)n * 32 + lane] = v;
            }
        }
    }
}

__global__ void __launch_bounds__(256) kC(const float* __restrict__ gam,
                                          const float* __restrict__ bet,
                                          const float* __restrict__ fcW,
                                          int layer, int final_layer,
                                          float* __restrict__ out) {
    __shared__ float fw[640];
    __shared__ float sA[64], sB[64];
    int tid = threadIdx.x;
    const float* fsrc = fcW + (layer + 1) * 640;
    for (int i = tid; i < 640; i += 256) fw[i] = fsrc[i];
    if (tid < 64) {
        float s = g_stats[layer * 256 + 128 + tid];
        float q = g_stats[layer * 256 + 192 + tid];
        float mu = s * (1.f / NN);
        float var = q * (1.f / NN) - mu * mu;
        float a = rsqrtf(var + 1e-5f) * gam[tid];
        sA[tid] = a;
        sB[tid] = bet[tid] - mu * a;
    }
    __syncthreads();
    int n = blockIdx.x * 256 + tid;
    if (n >= NN) return;
    float o[10];
#pragma unroll
    for (int c = 0; c < 10; c++) o[c] = out[n * 10 + c];
    const float4* z4 = ((const float4*)g_z2) + (size_t)n * 16;
    float4* hout = ((float4*)g_h) + (size_t)n * 16;
#pragma unroll
    for (int kk = 0; kk < 16; kk++) {
        float4 v = z4[kk];
        int k0 = kk * 4;
        float h0 = fmaxf(fmaf(v.x, sA[k0 + 0], sB[k0 + 0]), 0.f);
        float h1 = fmaxf(fmaf(v.y, sA[k0 + 1], sB[k0 + 1]), 0.f);
        float h2 = fmaxf(fmaf(v.z, sA[k0 + 2], sB[k0 + 2]), 0.f);
        float h3 = fmaxf(fmaf(v.w, sA[k0 + 3], sB[k0 + 3]), 0.f);
        if (!final_layer) hout[kk] = make_float4(h0, h1, h2, h3);
        const float* r0 = fw + k0 * 10;
#pragma unroll
        for (int c = 0; c < 10; c++)
            o[c] += h0 * r0[c] + h1 * r0[10 + c] + h2 * r0[20 + c] + h3 * r0[30 + c];
    }
    if (final_layer) {
        float m = -1e30f;
#pragma unroll
        for (int c = 0; c < 10; c++) m = fmaxf(m, o[c]);
        float s = 0.f;
#pragma unroll
        for (int c = 0; c < 10; c++) s += expf(o[c] - m);
        float lse = m + logf(s);
#pragma unroll
        for (int c = 0; c < 10; c++) o[c] -= lse;
    }
#pragma unroll
    for (int c = 0; c < 10; c++) out[n * 10 + c] = o[c];
}

extern "C" void kernel_launch(void* const* d_in, const int* in_sizes, int n_in,
                              void* d_out, int out_size) {
    const float* x   = (const float*)d_in[0];
    const int*   ei  = (const int*)d_in[1];
    const float* W1  = (const float*)d_in[2];
    const float* b1  = (const float*)d_in[3];
    const float* g1  = (const float*)d_in[4];
    const float* be1 = (const float*)d_in[5];
    const float* W2  = (const float*)d_in[6];
    const float* b2  = (const float*)d_in[7];
    const float* gbn = (const float*)d_in[8];
    const float* bbn = (const float*)d_in[9];
    const float* fcW = (const float*)d_in[10];
    const float* fcb = (const float*)d_in[11];
    float* out = (float*)d_out;

    const int GB  = (NN * 32 + 255) / 256;
    const int GGB = (NN + GNPB - 1) / GNPB;
    const int CB  = (NN + 255) / 256;

    kzero<<<(NN + 1023) / 1024, 1024>>>();
    kfill<<<(EE + 255) / 256, 256>>>(ei);
    kinit<<<CB, 256>>>(x, fcW, fcb, out);
    for (int l = 0; l < LL; l++) {
        int use_x = (l == 0) ? 1 : 0;
        kgather<<<GB, 256>>>(x, use_x);
        kG<<<GGB, 128>>>(W1 + l * 4096, b1 + l * 64, nullptr, nullptr, l, 0);
        kG<<<GGB, 128>>>(W2 + l * 4096, b2 + l * 64, g1 + l * 64, be1 + l * 64, l, 1);
        kC<<<CB, 256>>>(gbn + l * 64, bbn + l * 64, fcW, l, (l == LL - 1) ? 1 : 0, out);
    }
}